// round 10
// baseline (speedup 1.0000x reference)
#include <cuda_runtime.h>
#include <cuda_bf16.h>
#include <cstdint>

// ---------------- problem constants ----------------
#define NB   8
#define NC   2048
#define NF   8192
#define CDIM 256
#define CS   64
#define OUTD 256
#define MTOT (NB*NF)        // 65536
#define K1   (CDIM+CS)      // 320
#define HSIZE (MTOT*OUTD)
#define NKB1 20             // K1/16 k-blocks for GEMM1
#define NKB2 16             // 256/16 k-blocks for GEMM2
#define NNB  32             // 256/8 n-blocks

// ---------------- scratch (static device globals) ----------------
__device__ int   g_idx[MTOT*3];
__device__ float g_w[MTOT*3];
__device__ __align__(16) uint32_t g_hfrag_hi[(MTOT/16)*NKB2*128];
__device__ __align__(16) uint32_t g_hfrag_lo[(MTOT/16)*NKB2*128];
__device__ __align__(16) uint32_t g_w1f_hi[NNB*NKB1*64];
__device__ __align__(16) uint32_t g_w1f_lo[NNB*NKB1*64];
__device__ __align__(16) uint32_t g_w2f_hi[NNB*NKB2*64];
__device__ __align__(16) uint32_t g_w2f_lo[NNB*NKB2*64];

// ---------------- helpers ----------------
__device__ __forceinline__ uint32_t smem_u32(const void* p) {
    uint32_t a;
    asm("{ .reg .u64 t; cvta.to.shared.u64 t, %1; cvt.u32.u64 %0, t; }" : "=r"(a) : "l"(p));
    return a;
}

#define LDSM_X4(r0, r1, r2, r3, addr) \
    asm volatile("ldmatrix.sync.aligned.m8n8.x4.shared.b16 {%0,%1,%2,%3}, [%4];" \
        : "=r"(r0), "=r"(r1), "=r"(r2), "=r"(r3) : "r"(addr))

#define MMA_BF16(d, a, b0, b1) \
    asm volatile("mma.sync.aligned.m16n8k16.row.col.f32.bf16.bf16.f32 " \
        "{%0,%1,%2,%3}, {%4,%5,%6,%7}, {%8,%9}, {%0,%1,%2,%3};" \
        : "+f"((d)[0]), "+f"((d)[1]), "+f"((d)[2]), "+f"((d)[3]) \
        : "r"((a)[0]), "r"((a)[1]), "r"((a)[2]), "r"((a)[3]), "r"(b0), "r"(b1))

__device__ __forceinline__ void split2(float v0, float v1, uint32_t& hi, uint32_t& lo) {
    __nv_bfloat16 h0 = __float2bfloat16(v0);
    __nv_bfloat16 h1 = __float2bfloat16(v1);
    __nv_bfloat16 l0 = __float2bfloat16(v0 - __bfloat162float(h0));
    __nv_bfloat16 l1 = __float2bfloat16(v1 - __bfloat162float(h1));
    hi = ((uint32_t)__bfloat16_as_ushort(h1) << 16) | (uint32_t)__bfloat16_as_ushort(h0);
    lo = ((uint32_t)__bfloat16_as_ushort(l1) << 16) | (uint32_t)__bfloat16_as_ushort(l0);
}

// strict-> insertion keeps first-seen on ties (matches sequential min-scan)
#define INS3(sv, jj) do { \
    float _s = (sv); int _j = (jj); \
    if (_s > s2) { \
        if (_s > s1) { \
            s2 = s1; i2 = i1; \
            if (_s > s0) { s1 = s0; i1 = i0; s0 = _s; i0 = _j; } \
            else         { s1 = _s; i1 = _j; } \
        } else { s2 = _s; i2 = _j; } \
    } \
} while (0)

// ---------------- fused misc: knn (0..1023), prep (1024..1103), aux (1104..1871) ----------------
__global__ void misc_kernel(const float* __restrict__ pos,
                            const float* __restrict__ pos_skip,
                            const int*  __restrict__ batch_skip,
                            const float* __restrict__ W1,
                            const float* __restrict__ W2,
                            float* __restrict__ out) {
    __shared__ float sx[NC], sy[NC], sz[NC], sw[NC];
    int blk = blockIdx.x;
    int tid = threadIdx.x;

    if (blk < 1024) {
        // ---- KNN (K=3): 64 points/block, 4 threads/point ----
        int b = blk >> 7;            // 128 blocks per cloud
        int blk_in = blk & 127;
        const float* cp = pos + (size_t)b * NC * 3;
        for (int i = tid; i < NC; i += 256) {
            float cx = cp[i*3+0], cy = cp[i*3+1], cz = cp[i*3+2];
            sx[i] = cx; sy[i] = cy; sz[i] = cz;
            sw[i] = -0.5f * (cx*cx + cy*cy + cz*cz);
        }
        __syncthreads();

        int pl = tid >> 2;           // point within block: 0..63
        int q  = tid & 3;            // segment id
        int p = b * NF + blk_in * 64 + pl;
        float fx = pos_skip[p*3+0], fy = pos_skip[p*3+1], fz = pos_skip[p*3+2];

        float s0 = -1e30f, s1 = -1e30f, s2 = -1e30f;
        int   i0 = 0,      i1 = 0,      i2 = 0;

        int jbeg = q * 512;
        #pragma unroll 2
        for (int j = jbeg; j < jbeg + 512; j += 4) {
            float4 X = *(const float4*)&sx[j];
            float4 Y = *(const float4*)&sy[j];
            float4 Z = *(const float4*)&sz[j];
            float4 W = *(const float4*)&sw[j];
            float sa = fmaf(fz, Z.x, fmaf(fy, Y.x, fmaf(fx, X.x, W.x)));
            float sb = fmaf(fz, Z.y, fmaf(fy, Y.y, fmaf(fx, X.y, W.y)));
            float sc = fmaf(fz, Z.z, fmaf(fy, Y.z, fmaf(fx, X.z, W.z)));
            float sd = fmaf(fz, Z.w, fmaf(fy, Y.w, fmaf(fx, X.w, W.w)));
            float smax = fmaxf(fmaxf(sa, sb), fmaxf(sc, sd));
            if (smax > s2) {
                INS3(sa, j+0);
                INS3(sb, j+1);
                INS3(sc, j+2);
                INS3(sd, j+3);
            }
        }

        // ---- merge 4 segments (ascending q order keeps tie stability) ----
        const unsigned mask = 0xFFFFFFFFu;
        #pragma unroll
        for (int src = 1; src < 4; src++) {
            float t0 = __shfl_down_sync(mask, s0, src);
            float t1 = __shfl_down_sync(mask, s1, src);
            float t2 = __shfl_down_sync(mask, s2, src);
            int   j0 = __shfl_down_sync(mask, i0, src);
            int   j1 = __shfl_down_sync(mask, i1, src);
            int   j2 = __shfl_down_sync(mask, i2, src);
            if (q == 0) {
                INS3(t0, j0);
                INS3(t1, j1);
                INS3(t2, j2);
            }
        }

        if (q == 0) {
            // exact distances for the 3 winners (matches reference arithmetic)
            float dx, dy, dz;
            dx = fx - sx[i0]; dy = fy - sy[i0]; dz = fz - sz[i0];
            float d0 = dx*dx + dy*dy + dz*dz;
            dx = fx - sx[i1]; dy = fy - sy[i1]; dz = fz - sz[i1];
            float d1 = dx*dx + dy*dy + dz*dz;
            dx = fx - sx[i2]; dy = fy - sy[i2]; dz = fz - sz[i2];
            float d2 = dx*dx + dy*dy + dz*dz;
            float w0 = 1.0f / fmaxf(d0, 1e-16f);
            float w1 = 1.0f / fmaxf(d1, 1e-16f);
            float w2 = 1.0f / fmaxf(d2, 1e-16f);
            float inv = 1.0f / (w0 + w1 + w2);
            g_idx[p*3+0] = b*NC + i0;
            g_idx[p*3+1] = b*NC + i1;
            g_idx[p*3+2] = b*NC + i2;
            g_w[p*3+0] = w0 * inv;
            g_w[p*3+1] = w1 * inv;
            g_w[p*3+2] = w2 * inv;
        }
    } else if (blk < 1024 + 80) {
        // ---- weight prep: W^T -> B-fragment hi/lo ----
        int t = (blk - 1024) * 256 + tid;
        if (t < NNB * NKB1 * 32) {
            int lane = t & 31;
            int kb = (t >> 5) % NKB1;
            int nb = t / (32 * NKB1);
            int n = nb*8 + (lane >> 2);
            int k0 = kb*16 + (lane & 3)*2;
            float v0 = W1[(k0+0)*OUTD + n], v1 = W1[(k0+1)*OUTD + n];
            float v8 = W1[(k0+8)*OUTD + n], v9 = W1[(k0+9)*OUTD + n];
            uint32_t h0, l0, h1, l1;
            split2(v0, v1, h0, l0);
            split2(v8, v9, h1, l1);
            int idx = (nb*NKB1 + kb)*64 + lane*2;
            g_w1f_hi[idx] = h0; g_w1f_hi[idx+1] = h1;
            g_w1f_lo[idx] = l0; g_w1f_lo[idx+1] = l1;
        }
        if (t < NNB * NKB2 * 32) {
            int lane = t & 31;
            int kb = (t >> 5) & 15;
            int nb = t >> 9;
            int n = nb*8 + (lane >> 2);
            int k0 = kb*16 + (lane & 3)*2;
            float v0 = W2[(k0+0)*OUTD + n], v1 = W2[(k0+1)*OUTD + n];
            float v8 = W2[(k0+8)*OUTD + n], v9 = W2[(k0+9)*OUTD + n];
            uint32_t h0, l0, h1, l1;
            split2(v0, v1, h0, l0);
            split2(v8, v9, h1, l1);
            int idx = (nb*NKB2 + kb)*64 + lane*2;
            g_w2f_hi[idx] = h0; g_w2f_hi[idx+1] = h1;
            g_w2f_lo[idx] = l0; g_w2f_lo[idx+1] = l1;
        }
    } else {
        // ---- aux tail: pos_skip + batch_skip ----
        int i = (blk - 1104) * 256 + tid;
        if (i < MTOT*3) out[HSIZE + i] = pos_skip[i];
        if (i < MTOT)   out[HSIZE + MTOT*3 + i] = (float)batch_skip[i];
    }
}

// ---------------- GEMM1: pipelined gather+interp + Linear1 + ReLU -> h fragments ----------------
#define RS 40   // smem row stride (bf16)

__global__ __launch_bounds__(256, 2)
void gemm1_kernel(const float* __restrict__ x,
                  const float* __restrict__ x_skip,
                  const float* __restrict__ b1) {
    __shared__ __nv_bfloat16 As_hi[2][64*RS], As_lo[2][64*RS];

    int tid = threadIdx.x;
    int wid = tid >> 5;
    int lane = tid & 31;
    int warp_m = wid & 1;      // 2 m-strips of 32 rows
    int warp_n = wid >> 1;     // 4 n-quarters of 64 cols
    int bm = blockIdx.x * 64;

    int lrow = tid >> 2;       // 0..63
    int koff = (tid & 3) * 8;  // 0,8,16,24
    int r = bm + lrow;
    int i0 = g_idx[r*3+0] * CDIM, i1 = g_idx[r*3+1] * CDIM, i2 = g_idx[r*3+2] * CDIM;
    float w0 = g_w[r*3+0], w1 = g_w[r*3+1], w2 = g_w[r*3+2];
    int sbase = lrow * RS + koff;

    uint32_t aOff = (uint32_t)(((warp_m*32 + (lane & 15)) * RS + (lane >> 4) * 8) * 2);
    uint32_t sH[2] = { smem_u32(As_hi[0]) + aOff, smem_u32(As_hi[1]) + aOff };
    uint32_t sL[2] = { smem_u32(As_lo[0]) + aOff, smem_u32(As_lo[1]) + aOff };

    float acc[2][8][4];
    #pragma unroll
    for (int i = 0; i < 2; i++)
        #pragma unroll
        for (int j = 0; j < 8; j++)
            #pragma unroll
            for (int q = 0; q < 4; q++) acc[i][j][q] = 0.0f;

    // ---- prologue: build chunk 0 into buf 0 ----
    {
        float4 a0 = *(const float4*)(x + i0 + koff);
        float4 a1 = *(const float4*)(x + i0 + koff + 4);
        float4 b0 = *(const float4*)(x + i1 + koff);
        float4 b1v = *(const float4*)(x + i1 + koff + 4);
        float4 c0 = *(const float4*)(x + i2 + koff);
        float4 c1 = *(const float4*)(x + i2 + koff + 4);
        uint32_t hp[4], lp[4];
        split2(w0*a0.x + w1*b0.x + w2*c0.x,  w0*a0.y + w1*b0.y + w2*c0.y,  hp[0], lp[0]);
        split2(w0*a0.z + w1*b0.z + w2*c0.z,  w0*a0.w + w1*b0.w + w2*c0.w,  hp[1], lp[1]);
        split2(w0*a1.x + w1*b1v.x + w2*c1.x, w0*a1.y + w1*b1v.y + w2*c1.y, hp[2], lp[2]);
        split2(w0*a1.z + w1*b1v.z + w2*c1.z, w0*a1.w + w1*b1v.w + w2*c1.w, hp[3], lp[3]);
        *(uint4*)(As_hi[0] + sbase) = make_uint4(hp[0], hp[1], hp[2], hp[3]);
        *(uint4*)(As_lo[0] + sbase) = make_uint4(lp[0], lp[1], lp[2], lp[3]);
    }
    __syncthreads();

    for (int c = 0; c < 10; c++) {
        int buf = c & 1;
        float4 ga0, ga1, gb0, gb1, gc0, gc1;
        bool have_next = (c + 1 < 10);
        bool next_is_x = ((c + 1) * 32 < CDIM);
        if (have_next) {
            if (next_is_x) {
                int k = (c + 1) * 32 + koff;
                ga0 = *(const float4*)(x + i0 + k);
                ga1 = *(const float4*)(x + i0 + k + 4);
                gb0 = *(const float4*)(x + i1 + k);
                gb1 = *(const float4*)(x + i1 + k + 4);
                gc0 = *(const float4*)(x + i2 + k);
                gc1 = *(const float4*)(x + i2 + k + 4);
            } else {
                int ks = (c + 1) * 32 - CDIM + koff;
                ga0 = *(const float4*)(x_skip + (size_t)r * CS + ks);
                ga1 = *(const float4*)(x_skip + (size_t)r * CS + ks + 4);
            }
        }

        #pragma unroll
        for (int ks = 0; ks < 2; ks++) {
            int kb = c*2 + ks;
            uint32_t ko = ks * 32;
            uint32_t ah[2][4], al[2][4];
            #pragma unroll
            for (int mt = 0; mt < 2; mt++) {
                LDSM_X4(ah[mt][0], ah[mt][1], ah[mt][2], ah[mt][3], sH[buf] + mt*16*RS*2 + ko);
                LDSM_X4(al[mt][0], al[mt][1], al[mt][2], al[mt][3], sL[buf] + mt*16*RS*2 + ko);
            }
            #pragma unroll
            for (int nb = 0; nb < 8; nb++) {
                int nblock = warp_n*8 + nb;
                uint2 bh = *(const uint2*)&g_w1f_hi[(nblock*NKB1 + kb)*64 + lane*2];
                uint2 bl = *(const uint2*)&g_w1f_lo[(nblock*NKB1 + kb)*64 + lane*2];
                #pragma unroll
                for (int mt = 0; mt < 2; mt++) {
                    float* d = acc[mt][nb];
                    MMA_BF16(d, ah[mt], bh.x, bh.y);
                    MMA_BF16(d, ah[mt], bl.x, bl.y);
                    MMA_BF16(d, al[mt], bh.x, bh.y);
                }
            }
        }

        if (have_next) {
            float v[8];
            if (next_is_x) {
                v[0] = w0*ga0.x + w1*gb0.x + w2*gc0.x;
                v[1] = w0*ga0.y + w1*gb0.y + w2*gc0.y;
                v[2] = w0*ga0.z + w1*gb0.z + w2*gc0.z;
                v[3] = w0*ga0.w + w1*gb0.w + w2*gc0.w;
                v[4] = w0*ga1.x + w1*gb1.x + w2*gc1.x;
                v[5] = w0*ga1.y + w1*gb1.y + w2*gc1.y;
                v[6] = w0*ga1.z + w1*gb1.z + w2*gc1.z;
                v[7] = w0*ga1.w + w1*gb1.w + w2*gc1.w;
            } else {
                v[0] = ga0.x; v[1] = ga0.y; v[2] = ga0.z; v[3] = ga0.w;
                v[4] = ga1.x; v[5] = ga1.y; v[6] = ga1.z; v[7] = ga1.w;
            }
            uint32_t hp[4], lp[4];
            split2(v[0], v[1], hp[0], lp[0]);
            split2(v[2], v[3], hp[1], lp[1]);
            split2(v[4], v[5], hp[2], lp[2]);
            split2(v[6], v[7], hp[3], lp[3]);
            *(uint4*)(As_hi[buf^1] + sbase) = make_uint4(hp[0], hp[1], hp[2], hp[3]);
            *(uint4*)(As_lo[buf^1] + sbase) = make_uint4(lp[0], lp[1], lp[2], lp[3]);
        }
        __syncthreads();
    }

    // ---- epilogue: bias + ReLU -> h A-fragments ----
    #pragma unroll
    for (int mt = 0; mt < 2; mt++) {
        int mblock = blockIdx.x*4 + warp_m*2 + mt;
        #pragma unroll
        for (int fp = 0; fp < 4; fp++) {
            int f0 = 2*fp, f1 = 2*fp + 1;
            int kbh = warp_n*4 + fp;
            int col0 = (warp_n*8 + f0)*8 + (lane & 3)*2;
            float2 bb0 = *(const float2*)(b1 + col0);
            float2 bb1 = *(const float2*)(b1 + col0 + 8);
            float v0 = fmaxf(acc[mt][f0][0] + bb0.x, 0.0f);
            float v1 = fmaxf(acc[mt][f0][1] + bb0.y, 0.0f);
            float v2 = fmaxf(acc[mt][f0][2] + bb0.x, 0.0f);
            float v3 = fmaxf(acc[mt][f0][3] + bb0.y, 0.0f);
            float v4 = fmaxf(acc[mt][f1][0] + bb1.x, 0.0f);
            float v5 = fmaxf(acc[mt][f1][1] + bb1.y, 0.0f);
            float v6 = fmaxf(acc[mt][f1][2] + bb1.x, 0.0f);
            float v7 = fmaxf(acc[mt][f1][3] + bb1.y, 0.0f);
            uint32_t a0h, a0l, a1h, a1l, a2h, a2l, a3h, a3l;
            split2(v0, v1, a0h, a0l);
            split2(v2, v3, a1h, a1l);
            split2(v4, v5, a2h, a2l);
            split2(v6, v7, a3h, a3l);
            int fidx = (mblock*NKB2 + kbh)*32 + lane;
            ((uint4*)g_hfrag_hi)[fidx] = make_uint4(a0h, a1h, a2h, a3h);
            ((uint4*)g_hfrag_lo)[fidx] = make_uint4(a0l, a1l, a2l, a3l);
        }
    }
}

// ---------------- GEMM2: Linear2 + ReLU, fragment path with reg double-buffer ----------------
__global__ __launch_bounds__(256, 2)
void gemm2_kernel(const float* __restrict__ b2, float* __restrict__ out) {
    int tid = threadIdx.x;
    int wid = tid >> 5;
    int lane = tid & 31;
    int g = blockIdx.x * 8 + wid;
    int mstrip = g >> 2;
    int nq = g & 3;

    const uint4* HF = (const uint4*)g_hfrag_hi;
    const uint4* LF = (const uint4*)g_hfrag_lo;
    int mb0 = mstrip * 2;

    float acc[2][8][4];
    #pragma unroll
    for (int i = 0; i < 2; i++)
        #pragma unroll
        for (int j = 0; j < 8; j++)
            #pragma unroll
            for (int q = 0; q < 4; q++) acc[i][j][q] = 0.0f;

    uint4 th[2], tl[2];
    #pragma unroll
    for (int mt = 0; mt < 2; mt++) {
        th[mt] = HF[((mb0 + mt)*NKB2 + 0)*32 + lane];
        tl[mt] = LF[((mb0 + mt)*NKB2 + 0)*32 + lane];
    }

    for (int kb = 0; kb < NKB2; kb++) {
        uint32_t ah[2][4], al[2][4];
        #pragma unroll
        for (int mt = 0; mt < 2; mt++) {
            ah[mt][0] = th[mt].x; ah[mt][1] = th[mt].y; ah[mt][2] = th[mt].z; ah[mt][3] = th[mt].w;
            al[mt][0] = tl[mt].x; al[mt][1] = tl[mt].y; al[mt][2] = tl[mt].z; al[mt][3] = tl[mt].w;
        }
        if (kb + 1 < NKB2) {
            #pragma unroll
            for (int mt = 0; mt < 2; mt++) {
                th[mt] = HF[((mb0 + mt)*NKB2 + kb + 1)*32 + lane];
                tl[mt] = LF[((mb0 + mt)*NKB2 + kb + 1)*32 + lane];
            }
        }
        #pragma unroll
        for (int nb = 0; nb < 8; nb++) {
            int nblock = nq*8 + nb;
            uint2 bh = *(const uint2*)&g_w2f_hi[(nblock*NKB2 + kb)*64 + lane*2];
            uint2 bl = *(const uint2*)&g_w2f_lo[(nblock*NKB2 + kb)*64 + lane*2];
            #pragma unroll
            for (int mt = 0; mt < 2; mt++) {
                float* d = acc[mt][nb];
                MMA_BF16(d, ah[mt], bh.x, bh.y);
                MMA_BF16(d, ah[mt], bl.x, bl.y);
                MMA_BF16(d, al[mt], bh.x, bh.y);
            }
        }
    }

    #pragma unroll
    for (int mt = 0; mt < 2; mt++) {
        int r0 = mstrip*32 + mt*16 + (lane >> 2);
        #pragma unroll
        for (int nb = 0; nb < 8; nb++) {
            int col = (nq*8 + nb)*8 + (lane & 3)*2;
            float2 bb = *(const float2*)(b2 + col);
            float2 o0, o1;
            o0.x = fmaxf(acc[mt][nb][0] + bb.x, 0.0f);
            o0.y = fmaxf(acc[mt][nb][1] + bb.y, 0.0f);
            o1.x = fmaxf(acc[mt][nb][2] + bb.x, 0.0f);
            o1.y = fmaxf(acc[mt][nb][3] + bb.y, 0.0f);
            *(float2*)(out + (size_t)r0 * OUTD + col) = o0;
            *(float2*)(out + (size_t)(r0+8) * OUTD + col) = o1;
        }
    }
}

// ---------------- launch ----------------
extern "C" void kernel_launch(void* const* d_in, const int* in_sizes, int n_in,
                              void* d_out, int out_size) {
    const float* x          = (const float*)d_in[0];
    const float* pos        = (const float*)d_in[1];
    const float* x_skip     = (const float*)d_in[3];
    const float* pos_skip   = (const float*)d_in[4];
    const int*   batch_skip = (const int*)d_in[5];
    const float* W1         = (const float*)d_in[6];
    const float* b1         = (const float*)d_in[7];
    const float* W2         = (const float*)d_in[8];
    const float* b2         = (const float*)d_in[9];
    float* out = (float*)d_out;

    // knn: 1024 blocks, prep: 80 blocks, aux: 768 blocks
    misc_kernel<<<1024 + 80 + 768, 256>>>(pos, pos_skip, batch_skip, W1, W2, out);
    gemm1_kernel<<<MTOT/64, 256>>>(x, x_skip, b1);
    gemm2_kernel<<<1024, 256>>>(b2, out);
}

// round 11
// speedup vs baseline: 1.3405x; 1.3405x over previous
#include <cuda_runtime.h>
#include <cuda_bf16.h>
#include <cstdint>

// ---------------- problem constants ----------------
#define NB   8
#define NC   2048
#define NF   8192
#define CDIM 256
#define CS   64
#define OUTD 256
#define MTOT (NB*NF)        // 65536
#define K1   (CDIM+CS)      // 320
#define HSIZE (MTOT*OUTD)
#define NKB1 20             // K1/16 k-blocks for GEMM1
#define NKB2 16             // 256/16 k-blocks for GEMM2
#define NNB  32             // 256/8 n-blocks

// ---------------- scratch (static device globals) ----------------
__device__ int   g_idx[MTOT*3];
__device__ float g_w[MTOT*3];
__device__ __align__(16) uint32_t g_hfrag_hi[(MTOT/16)*NKB2*128];
__device__ __align__(16) uint32_t g_hfrag_lo[(MTOT/16)*NKB2*128];
__device__ __align__(16) uint32_t g_w1f_hi[NNB*NKB1*64];
__device__ __align__(16) uint32_t g_w1f_lo[NNB*NKB1*64];
__device__ __align__(16) uint32_t g_w2f_hi[NNB*NKB2*64];
__device__ __align__(16) uint32_t g_w2f_lo[NNB*NKB2*64];

// ---------------- helpers ----------------
__device__ __forceinline__ uint32_t smem_u32(const void* p) {
    uint32_t a;
    asm("{ .reg .u64 t; cvta.to.shared.u64 t, %1; cvt.u32.u64 %0, t; }" : "=r"(a) : "l"(p));
    return a;
}

#define LDSM_X4(r0, r1, r2, r3, addr) \
    asm volatile("ldmatrix.sync.aligned.m8n8.x4.shared.b16 {%0,%1,%2,%3}, [%4];" \
        : "=r"(r0), "=r"(r1), "=r"(r2), "=r"(r3) : "r"(addr))

#define MMA_BF16(d, a, b0, b1) \
    asm volatile("mma.sync.aligned.m16n8k16.row.col.f32.bf16.bf16.f32 " \
        "{%0,%1,%2,%3}, {%4,%5,%6,%7}, {%8,%9}, {%0,%1,%2,%3};" \
        : "+f"((d)[0]), "+f"((d)[1]), "+f"((d)[2]), "+f"((d)[3]) \
        : "r"((a)[0]), "r"((a)[1]), "r"((a)[2]), "r"((a)[3]), "r"(b0), "r"(b1))

__device__ __forceinline__ void split2(float v0, float v1, uint32_t& hi, uint32_t& lo) {
    __nv_bfloat16 h0 = __float2bfloat16(v0);
    __nv_bfloat16 h1 = __float2bfloat16(v1);
    __nv_bfloat16 l0 = __float2bfloat16(v0 - __bfloat162float(h0));
    __nv_bfloat16 l1 = __float2bfloat16(v1 - __bfloat162float(h1));
    hi = ((uint32_t)__bfloat16_as_ushort(h1) << 16) | (uint32_t)__bfloat16_as_ushort(h0);
    lo = ((uint32_t)__bfloat16_as_ushort(l1) << 16) | (uint32_t)__bfloat16_as_ushort(l0);
}

__device__ __forceinline__ void ins3(float s, int j,
                                     float& s0, float& s1, float& s2,
                                     int& i0, int& i1, int& i2) {
    if (s > s2) {
        if (s > s1) {
            s2 = s1; i2 = i1;
            if (s > s0) { s1 = s0; i1 = i0; s0 = s; i0 = j; }
            else        { s1 = s;  i1 = j; }
        } else { s2 = s; i2 = j; }
    }
}

// ---------------- fused misc: knn (0..127), prep (128..207), aux (208..975) ----------------
__global__ void misc_kernel(const float* __restrict__ pos,
                            const float* __restrict__ pos_skip,
                            const int*  __restrict__ batch_skip,
                            const float* __restrict__ W1,
                            const float* __restrict__ W2,
                            float* __restrict__ out) {
    __shared__ float sx[NC], sy[NC], sz[NC], sw[NC];
    int blk = blockIdx.x;
    int tid = threadIdx.x;

    if (blk < 128) {
        // ---- KNN (K=3): 512 points/block, 2 points/thread, broadcast scan ----
        int b = blk >> 4;            // 16 blocks per cloud
        int blk_in = blk & 15;
        const float* cp = pos + (size_t)b * NC * 3;
        for (int i = tid; i < NC; i += 256) {
            float cx = cp[i*3+0], cy = cp[i*3+1], cz = cp[i*3+2];
            sx[i] = cx; sy[i] = cy; sz[i] = cz;
            sw[i] = -0.5f * (cx*cx + cy*cy + cz*cz);
        }
        __syncthreads();

        int base = b * NF + blk_in * 512;
        int p0 = base + tid;
        int p1 = base + 256 + tid;
        float fx0 = pos_skip[p0*3+0], fy0 = pos_skip[p0*3+1], fz0 = pos_skip[p0*3+2];
        float fx1 = pos_skip[p1*3+0], fy1 = pos_skip[p1*3+1], fz1 = pos_skip[p1*3+2];

        float a0 = -1e30f, a1 = -1e30f, a2 = -1e30f;   // point 0 top-3 scores
        int   ai0 = 0,     ai1 = 0,     ai2 = 0;
        float c0 = -1e30f, c1 = -1e30f, c2 = -1e30f;   // point 1 top-3 scores
        int   ci0 = 0,     ci1 = 0,     ci2 = 0;

        #pragma unroll 2
        for (int j = 0; j < NC; j += 4) {
            float4 X = *(const float4*)&sx[j];
            float4 Y = *(const float4*)&sy[j];
            float4 Z = *(const float4*)&sz[j];
            float4 W = *(const float4*)&sw[j];
            // point 0
            {
                float sa = fmaf(fz0, Z.x, fmaf(fy0, Y.x, fmaf(fx0, X.x, W.x)));
                float sb = fmaf(fz0, Z.y, fmaf(fy0, Y.y, fmaf(fx0, X.y, W.y)));
                float sc = fmaf(fz0, Z.z, fmaf(fy0, Y.z, fmaf(fx0, X.z, W.z)));
                float sd = fmaf(fz0, Z.w, fmaf(fy0, Y.w, fmaf(fx0, X.w, W.w)));
                float smax = fmaxf(fmaxf(sa, sb), fmaxf(sc, sd));
                if (smax > a2) {
                    ins3(sa, j+0, a0, a1, a2, ai0, ai1, ai2);
                    ins3(sb, j+1, a0, a1, a2, ai0, ai1, ai2);
                    ins3(sc, j+2, a0, a1, a2, ai0, ai1, ai2);
                    ins3(sd, j+3, a0, a1, a2, ai0, ai1, ai2);
                }
            }
            // point 1
            {
                float sa = fmaf(fz1, Z.x, fmaf(fy1, Y.x, fmaf(fx1, X.x, W.x)));
                float sb = fmaf(fz1, Z.y, fmaf(fy1, Y.y, fmaf(fx1, X.y, W.y)));
                float sc = fmaf(fz1, Z.z, fmaf(fy1, Y.z, fmaf(fx1, X.z, W.z)));
                float sd = fmaf(fz1, Z.w, fmaf(fy1, Y.w, fmaf(fx1, X.w, W.w)));
                float smax = fmaxf(fmaxf(sa, sb), fmaxf(sc, sd));
                if (smax > c2) {
                    ins3(sa, j+0, c0, c1, c2, ci0, ci1, ci2);
                    ins3(sb, j+1, c0, c1, c2, ci0, ci1, ci2);
                    ins3(sc, j+2, c0, c1, c2, ci0, ci1, ci2);
                    ins3(sd, j+3, c0, c1, c2, ci0, ci1, ci2);
                }
            }
        }

        // exact distances + weights for winners
        {
            float dx, dy, dz;
            dx = fx0 - sx[ai0]; dy = fy0 - sy[ai0]; dz = fz0 - sz[ai0];
            float d0 = dx*dx + dy*dy + dz*dz;
            dx = fx0 - sx[ai1]; dy = fy0 - sy[ai1]; dz = fz0 - sz[ai1];
            float d1 = dx*dx + dy*dy + dz*dz;
            dx = fx0 - sx[ai2]; dy = fy0 - sy[ai2]; dz = fz0 - sz[ai2];
            float d2 = dx*dx + dy*dy + dz*dz;
            float w0 = 1.0f / fmaxf(d0, 1e-16f);
            float w1 = 1.0f / fmaxf(d1, 1e-16f);
            float w2 = 1.0f / fmaxf(d2, 1e-16f);
            float inv = 1.0f / (w0 + w1 + w2);
            g_idx[p0*3+0] = b*NC + ai0;
            g_idx[p0*3+1] = b*NC + ai1;
            g_idx[p0*3+2] = b*NC + ai2;
            g_w[p0*3+0] = w0 * inv;
            g_w[p0*3+1] = w1 * inv;
            g_w[p0*3+2] = w2 * inv;
        }
        {
            float dx, dy, dz;
            dx = fx1 - sx[ci0]; dy = fy1 - sy[ci0]; dz = fz1 - sz[ci0];
            float d0 = dx*dx + dy*dy + dz*dz;
            dx = fx1 - sx[ci1]; dy = fy1 - sy[ci1]; dz = fz1 - sz[ci1];
            float d1 = dx*dx + dy*dy + dz*dz;
            dx = fx1 - sx[ci2]; dy = fy1 - sy[ci2]; dz = fz1 - sz[ci2];
            float d2 = dx*dx + dy*dy + dz*dz;
            float w0 = 1.0f / fmaxf(d0, 1e-16f);
            float w1 = 1.0f / fmaxf(d1, 1e-16f);
            float w2 = 1.0f / fmaxf(d2, 1e-16f);
            float inv = 1.0f / (w0 + w1 + w2);
            g_idx[p1*3+0] = b*NC + ci0;
            g_idx[p1*3+1] = b*NC + ci1;
            g_idx[p1*3+2] = b*NC + ci2;
            g_w[p1*3+0] = w0 * inv;
            g_w[p1*3+1] = w1 * inv;
            g_w[p1*3+2] = w2 * inv;
        }
    } else if (blk < 128 + 80) {
        // ---- weight prep: W^T -> B-fragment hi/lo ----
        int t = (blk - 128) * 256 + tid;
        if (t < NNB * NKB1 * 32) {
            int lane = t & 31;
            int kb = (t >> 5) % NKB1;
            int nb = t / (32 * NKB1);
            int n = nb*8 + (lane >> 2);
            int k0 = kb*16 + (lane & 3)*2;
            float v0 = W1[(k0+0)*OUTD + n], v1 = W1[(k0+1)*OUTD + n];
            float v8 = W1[(k0+8)*OUTD + n], v9 = W1[(k0+9)*OUTD + n];
            uint32_t h0, l0, h1, l1;
            split2(v0, v1, h0, l0);
            split2(v8, v9, h1, l1);
            int idx = (nb*NKB1 + kb)*64 + lane*2;
            g_w1f_hi[idx] = h0; g_w1f_hi[idx+1] = h1;
            g_w1f_lo[idx] = l0; g_w1f_lo[idx+1] = l1;
        }
        if (t < NNB * NKB2 * 32) {
            int lane = t & 31;
            int kb = (t >> 5) & 15;
            int nb = t >> 9;
            int n = nb*8 + (lane >> 2);
            int k0 = kb*16 + (lane & 3)*2;
            float v0 = W2[(k0+0)*OUTD + n], v1 = W2[(k0+1)*OUTD + n];
            float v8 = W2[(k0+8)*OUTD + n], v9 = W2[(k0+9)*OUTD + n];
            uint32_t h0, l0, h1, l1;
            split2(v0, v1, h0, l0);
            split2(v8, v9, h1, l1);
            int idx = (nb*NKB2 + kb)*64 + lane*2;
            g_w2f_hi[idx] = h0; g_w2f_hi[idx+1] = h1;
            g_w2f_lo[idx] = l0; g_w2f_lo[idx+1] = l1;
        }
    } else {
        // ---- aux tail: pos_skip + batch_skip ----
        int i = (blk - 208) * 256 + tid;
        if (i < MTOT*3) out[HSIZE + i] = pos_skip[i];
        if (i < MTOT)   out[HSIZE + MTOT*3 + i] = (float)batch_skip[i];
    }
}

// ---------------- GEMM1: pipelined gather+interp + Linear1 + ReLU -> h fragments ----------------
#define RS 40   // smem row stride (bf16)

__global__ __launch_bounds__(256, 2)
void gemm1_kernel(const float* __restrict__ x,
                  const float* __restrict__ x_skip,
                  const float* __restrict__ b1) {
    __shared__ __nv_bfloat16 As_hi[2][64*RS], As_lo[2][64*RS];

    int tid = threadIdx.x;
    int wid = tid >> 5;
    int lane = tid & 31;
    int warp_m = wid & 1;      // 2 m-strips of 32 rows
    int warp_n = wid >> 1;     // 4 n-quarters of 64 cols
    int bm = blockIdx.x * 64;

    int lrow = tid >> 2;       // 0..63
    int koff = (tid & 3) * 8;  // 0,8,16,24
    int r = bm + lrow;
    int i0 = g_idx[r*3+0] * CDIM, i1 = g_idx[r*3+1] * CDIM, i2 = g_idx[r*3+2] * CDIM;
    float w0 = g_w[r*3+0], w1 = g_w[r*3+1], w2 = g_w[r*3+2];
    int sbase = lrow * RS + koff;

    uint32_t aOff = (uint32_t)(((warp_m*32 + (lane & 15)) * RS + (lane >> 4) * 8) * 2);
    uint32_t sH[2] = { smem_u32(As_hi[0]) + aOff, smem_u32(As_hi[1]) + aOff };
    uint32_t sL[2] = { smem_u32(As_lo[0]) + aOff, smem_u32(As_lo[1]) + aOff };

    float acc[2][8][4];
    #pragma unroll
    for (int i = 0; i < 2; i++)
        #pragma unroll
        for (int j = 0; j < 8; j++)
            #pragma unroll
            for (int q = 0; q < 4; q++) acc[i][j][q] = 0.0f;

    // ---- prologue: build chunk 0 into buf 0 ----
    {
        float4 a0 = *(const float4*)(x + i0 + koff);
        float4 a1 = *(const float4*)(x + i0 + koff + 4);
        float4 b0 = *(const float4*)(x + i1 + koff);
        float4 b1v = *(const float4*)(x + i1 + koff + 4);
        float4 c0 = *(const float4*)(x + i2 + koff);
        float4 c1 = *(const float4*)(x + i2 + koff + 4);
        uint32_t hp[4], lp[4];
        split2(w0*a0.x + w1*b0.x + w2*c0.x,  w0*a0.y + w1*b0.y + w2*c0.y,  hp[0], lp[0]);
        split2(w0*a0.z + w1*b0.z + w2*c0.z,  w0*a0.w + w1*b0.w + w2*c0.w,  hp[1], lp[1]);
        split2(w0*a1.x + w1*b1v.x + w2*c1.x, w0*a1.y + w1*b1v.y + w2*c1.y, hp[2], lp[2]);
        split2(w0*a1.z + w1*b1v.z + w2*c1.z, w0*a1.w + w1*b1v.w + w2*c1.w, hp[3], lp[3]);
        *(uint4*)(As_hi[0] + sbase) = make_uint4(hp[0], hp[1], hp[2], hp[3]);
        *(uint4*)(As_lo[0] + sbase) = make_uint4(lp[0], lp[1], lp[2], lp[3]);
    }
    __syncthreads();

    for (int c = 0; c < 10; c++) {
        int buf = c & 1;
        float4 ga0, ga1, gb0, gb1, gc0, gc1;
        bool have_next = (c + 1 < 10);
        bool next_is_x = ((c + 1) * 32 < CDIM);
        if (have_next) {
            if (next_is_x) {
                int k = (c + 1) * 32 + koff;
                ga0 = *(const float4*)(x + i0 + k);
                ga1 = *(const float4*)(x + i0 + k + 4);
                gb0 = *(const float4*)(x + i1 + k);
                gb1 = *(const float4*)(x + i1 + k + 4);
                gc0 = *(const float4*)(x + i2 + k);
                gc1 = *(const float4*)(x + i2 + k + 4);
            } else {
                int ks = (c + 1) * 32 - CDIM + koff;
                ga0 = *(const float4*)(x_skip + (size_t)r * CS + ks);
                ga1 = *(const float4*)(x_skip + (size_t)r * CS + ks + 4);
            }
        }

        #pragma unroll
        for (int ks = 0; ks < 2; ks++) {
            int kb = c*2 + ks;
            uint32_t ko = ks * 32;
            uint32_t ah[2][4], al[2][4];
            #pragma unroll
            for (int mt = 0; mt < 2; mt++) {
                LDSM_X4(ah[mt][0], ah[mt][1], ah[mt][2], ah[mt][3], sH[buf] + mt*16*RS*2 + ko);
                LDSM_X4(al[mt][0], al[mt][1], al[mt][2], al[mt][3], sL[buf] + mt*16*RS*2 + ko);
            }
            #pragma unroll
            for (int nb = 0; nb < 8; nb++) {
                int nblock = warp_n*8 + nb;
                uint2 bh = *(const uint2*)&g_w1f_hi[(nblock*NKB1 + kb)*64 + lane*2];
                uint2 bl = *(const uint2*)&g_w1f_lo[(nblock*NKB1 + kb)*64 + lane*2];
                #pragma unroll
                for (int mt = 0; mt < 2; mt++) {
                    float* d = acc[mt][nb];
                    MMA_BF16(d, ah[mt], bh.x, bh.y);
                    MMA_BF16(d, ah[mt], bl.x, bl.y);
                    MMA_BF16(d, al[mt], bh.x, bh.y);
                }
            }
        }

        if (have_next) {
            float v[8];
            if (next_is_x) {
                v[0] = w0*ga0.x + w1*gb0.x + w2*gc0.x;
                v[1] = w0*ga0.y + w1*gb0.y + w2*gc0.y;
                v[2] = w0*ga0.z + w1*gb0.z + w2*gc0.z;
                v[3] = w0*ga0.w + w1*gb0.w + w2*gc0.w;
                v[4] = w0*ga1.x + w1*gb1.x + w2*gc1.x;
                v[5] = w0*ga1.y + w1*gb1.y + w2*gc1.y;
                v[6] = w0*ga1.z + w1*gb1.z + w2*gc1.z;
                v[7] = w0*ga1.w + w1*gb1.w + w2*gc1.w;
            } else {
                v[0] = ga0.x; v[1] = ga0.y; v[2] = ga0.z; v[3] = ga0.w;
                v[4] = ga1.x; v[5] = ga1.y; v[6] = ga1.z; v[7] = ga1.w;
            }
            uint32_t hp[4], lp[4];
            split2(v[0], v[1], hp[0], lp[0]);
            split2(v[2], v[3], hp[1], lp[1]);
            split2(v[4], v[5], hp[2], lp[2]);
            split2(v[6], v[7], hp[3], lp[3]);
            *(uint4*)(As_hi[buf^1] + sbase) = make_uint4(hp[0], hp[1], hp[2], hp[3]);
            *(uint4*)(As_lo[buf^1] + sbase) = make_uint4(lp[0], lp[1], lp[2], lp[3]);
        }
        __syncthreads();
    }

    // ---- epilogue: bias + ReLU -> h A-fragments ----
    #pragma unroll
    for (int mt = 0; mt < 2; mt++) {
        int mblock = blockIdx.x*4 + warp_m*2 + mt;
        #pragma unroll
        for (int fp = 0; fp < 4; fp++) {
            int f0 = 2*fp, f1 = 2*fp + 1;
            int kbh = warp_n*4 + fp;
            int col0 = (warp_n*8 + f0)*8 + (lane & 3)*2;
            float2 bb0 = *(const float2*)(b1 + col0);
            float2 bb1 = *(const float2*)(b1 + col0 + 8);
            float v0 = fmaxf(acc[mt][f0][0] + bb0.x, 0.0f);
            float v1 = fmaxf(acc[mt][f0][1] + bb0.y, 0.0f);
            float v2 = fmaxf(acc[mt][f0][2] + bb0.x, 0.0f);
            float v3 = fmaxf(acc[mt][f0][3] + bb0.y, 0.0f);
            float v4 = fmaxf(acc[mt][f1][0] + bb1.x, 0.0f);
            float v5 = fmaxf(acc[mt][f1][1] + bb1.y, 0.0f);
            float v6 = fmaxf(acc[mt][f1][2] + bb1.x, 0.0f);
            float v7 = fmaxf(acc[mt][f1][3] + bb1.y, 0.0f);
            uint32_t a0h, a0l, a1h, a1l, a2h, a2l, a3h, a3l;
            split2(v0, v1, a0h, a0l);
            split2(v2, v3, a1h, a1l);
            split2(v4, v5, a2h, a2l);
            split2(v6, v7, a3h, a3l);
            int fidx = (mblock*NKB2 + kbh)*32 + lane;
            ((uint4*)g_hfrag_hi)[fidx] = make_uint4(a0h, a1h, a2h, a3h);
            ((uint4*)g_hfrag_lo)[fidx] = make_uint4(a0l, a1l, a2l, a3l);
        }
    }
}

// ---------------- GEMM2: Linear2 + ReLU, fragment path with reg double-buffer ----------------
__global__ __launch_bounds__(256, 2)
void gemm2_kernel(const float* __restrict__ b2, float* __restrict__ out) {
    int tid = threadIdx.x;
    int wid = tid >> 5;
    int lane = tid & 31;
    int g = blockIdx.x * 8 + wid;
    int mstrip = g >> 2;
    int nq = g & 3;

    const uint4* HF = (const uint4*)g_hfrag_hi;
    const uint4* LF = (const uint4*)g_hfrag_lo;
    int mb0 = mstrip * 2;

    float acc[2][8][4];
    #pragma unroll
    for (int i = 0; i < 2; i++)
        #pragma unroll
        for (int j = 0; j < 8; j++)
            #pragma unroll
            for (int q = 0; q < 4; q++) acc[i][j][q] = 0.0f;

    uint4 th[2], tl[2];
    #pragma unroll
    for (int mt = 0; mt < 2; mt++) {
        th[mt] = HF[((mb0 + mt)*NKB2 + 0)*32 + lane];
        tl[mt] = LF[((mb0 + mt)*NKB2 + 0)*32 + lane];
    }

    for (int kb = 0; kb < NKB2; kb++) {
        uint32_t ah[2][4], al[2][4];
        #pragma unroll
        for (int mt = 0; mt < 2; mt++) {
            ah[mt][0] = th[mt].x; ah[mt][1] = th[mt].y; ah[mt][2] = th[mt].z; ah[mt][3] = th[mt].w;
            al[mt][0] = tl[mt].x; al[mt][1] = tl[mt].y; al[mt][2] = tl[mt].z; al[mt][3] = tl[mt].w;
        }
        if (kb + 1 < NKB2) {
            #pragma unroll
            for (int mt = 0; mt < 2; mt++) {
                th[mt] = HF[((mb0 + mt)*NKB2 + kb + 1)*32 + lane];
                tl[mt] = LF[((mb0 + mt)*NKB2 + kb + 1)*32 + lane];
            }
        }
        #pragma unroll
        for (int nb = 0; nb < 8; nb++) {
            int nblock = nq*8 + nb;
            uint2 bh = *(const uint2*)&g_w2f_hi[(nblock*NKB2 + kb)*64 + lane*2];
            uint2 bl = *(const uint2*)&g_w2f_lo[(nblock*NKB2 + kb)*64 + lane*2];
            #pragma unroll
            for (int mt = 0; mt < 2; mt++) {
                float* d = acc[mt][nb];
                MMA_BF16(d, ah[mt], bh.x, bh.y);
                MMA_BF16(d, ah[mt], bl.x, bl.y);
                MMA_BF16(d, al[mt], bh.x, bh.y);
            }
        }
    }

    #pragma unroll
    for (int mt = 0; mt < 2; mt++) {
        int r0 = mstrip*32 + mt*16 + (lane >> 2);
        #pragma unroll
        for (int nb = 0; nb < 8; nb++) {
            int col = (nq*8 + nb)*8 + (lane & 3)*2;
            float2 bb = *(const float2*)(b2 + col);
            float2 o0, o1;
            o0.x = fmaxf(acc[mt][nb][0] + bb.x, 0.0f);
            o0.y = fmaxf(acc[mt][nb][1] + bb.y, 0.0f);
            o1.x = fmaxf(acc[mt][nb][2] + bb.x, 0.0f);
            o1.y = fmaxf(acc[mt][nb][3] + bb.y, 0.0f);
            *(float2*)(out + (size_t)r0 * OUTD + col) = o0;
            *(float2*)(out + (size_t)(r0+8) * OUTD + col) = o1;
        }
    }
}

// ---------------- launch ----------------
extern "C" void kernel_launch(void* const* d_in, const int* in_sizes, int n_in,
                              void* d_out, int out_size) {
    const float* x          = (const float*)d_in[0];
    const float* pos        = (const float*)d_in[1];
    const float* x_skip     = (const float*)d_in[3];
    const float* pos_skip   = (const float*)d_in[4];
    const int*   batch_skip = (const int*)d_in[5];
    const float* W1         = (const float*)d_in[6];
    const float* b1         = (const float*)d_in[7];
    const float* W2         = (const float*)d_in[8];
    const float* b2         = (const float*)d_in[9];
    float* out = (float*)d_out;

    // knn: 128 blocks, prep: 80 blocks, aux: 768 blocks
    misc_kernel<<<128 + 80 + 768, 256>>>(pos, pos_skip, batch_skip, W1, W2, out);
    gemm1_kernel<<<MTOT/64, 256>>>(x, x_skip, b1);
    gemm2_kernel<<<1024, 256>>>(b2, out);
}

// round 12
// speedup vs baseline: 1.5185x; 1.1327x over previous
#include <cuda_runtime.h>
#include <cuda_bf16.h>
#include <cstdint>

// ---------------- problem constants ----------------
#define NB   8
#define NC   2048
#define NF   8192
#define CDIM 256
#define CS   64
#define OUTD 256
#define MTOT (NB*NF)        // 65536
#define K1   (CDIM+CS)      // 320
#define HSIZE (MTOT*OUTD)
#define NKB1 20             // K1/16 k-blocks for GEMM1
#define NKB2 16             // 256/16 k-blocks for GEMM2
#define NNB  32             // 256/8 n-blocks

// ---------------- scratch (static device globals) ----------------
__device__ int   g_idx[MTOT*3];
__device__ float g_w[MTOT*3];
__device__ __align__(16) uint32_t g_hfrag_hi[(MTOT/16)*NKB2*128];
__device__ __align__(16) uint32_t g_hfrag_lo[(MTOT/16)*NKB2*128];
__device__ __align__(16) uint32_t g_w1f_hi[NNB*NKB1*64];
__device__ __align__(16) uint32_t g_w1f_lo[NNB*NKB1*64];
__device__ __align__(16) uint32_t g_w2f_hi[NNB*NKB2*64];
__device__ __align__(16) uint32_t g_w2f_lo[NNB*NKB2*64];

// ---------------- helpers ----------------
__device__ __forceinline__ uint32_t smem_u32(const void* p) {
    uint32_t a;
    asm("{ .reg .u64 t; cvta.to.shared.u64 t, %1; cvt.u32.u64 %0, t; }" : "=r"(a) : "l"(p));
    return a;
}

#define LDSM_X4(r0, r1, r2, r3, addr) \
    asm volatile("ldmatrix.sync.aligned.m8n8.x4.shared.b16 {%0,%1,%2,%3}, [%4];" \
        : "=r"(r0), "=r"(r1), "=r"(r2), "=r"(r3) : "r"(addr))

#define MMA_BF16(d, a, b0, b1) \
    asm volatile("mma.sync.aligned.m16n8k16.row.col.f32.bf16.bf16.f32 " \
        "{%0,%1,%2,%3}, {%4,%5,%6,%7}, {%8,%9}, {%0,%1,%2,%3};" \
        : "+f"((d)[0]), "+f"((d)[1]), "+f"((d)[2]), "+f"((d)[3]) \
        : "r"((a)[0]), "r"((a)[1]), "r"((a)[2]), "r"((a)[3]), "r"(b0), "r"(b1))

__device__ __forceinline__ void split2(float v0, float v1, uint32_t& hi, uint32_t& lo) {
    __nv_bfloat16 h0 = __float2bfloat16(v0);
    __nv_bfloat16 h1 = __float2bfloat16(v1);
    __nv_bfloat16 l0 = __float2bfloat16(v0 - __bfloat162float(h0));
    __nv_bfloat16 l1 = __float2bfloat16(v1 - __bfloat162float(h1));
    hi = ((uint32_t)__bfloat16_as_ushort(h1) << 16) | (uint32_t)__bfloat16_as_ushort(h0);
    lo = ((uint32_t)__bfloat16_as_ushort(l1) << 16) | (uint32_t)__bfloat16_as_ushort(l0);
}

__device__ __forceinline__ void ins3(float s, int j,
                                     float& s0, float& s1, float& s2,
                                     int& i0, int& i1, int& i2) {
    if (s > s2) {
        if (s > s1) {
            s2 = s1; i2 = i1;
            if (s > s0) { s1 = s0; i1 = i0; s0 = s; i0 = j; }
            else        { s1 = s;  i1 = j; }
        } else { s2 = s; i2 = j; }
    }
}

// ---------------- fused misc: knn (0..255), prep (256..335), aux (336..1103) ----------------
__global__ void misc_kernel(const float* __restrict__ pos,
                            const float* __restrict__ pos_skip,
                            const int*  __restrict__ batch_skip,
                            const float* __restrict__ W1,
                            const float* __restrict__ W2,
                            float* __restrict__ out) {
    __shared__ float sx[NC], sy[NC], sz[NC], sw[NC];
    int blk = blockIdx.x;
    int tid = threadIdx.x;

    if (blk < 256) {
        // ---- KNN (K=3): 256 points/block, 1 point/thread, broadcast scan ----
        int b = blk >> 5;            // 32 blocks per cloud
        int blk_in = blk & 31;
        const float* cp = pos + (size_t)b * NC * 3;
        for (int i = tid; i < NC; i += 256) {
            float cx = cp[i*3+0], cy = cp[i*3+1], cz = cp[i*3+2];
            sx[i] = cx; sy[i] = cy; sz[i] = cz;
            sw[i] = -0.5f * (cx*cx + cy*cy + cz*cz);
        }
        __syncthreads();

        int p = b * NF + blk_in * 256 + tid;
        float fx = pos_skip[p*3+0], fy = pos_skip[p*3+1], fz = pos_skip[p*3+2];

        float a0 = -1e30f, a1 = -1e30f, a2 = -1e30f;
        int   ai0 = 0,     ai1 = 0,     ai2 = 0;

        #pragma unroll 2
        for (int j = 0; j < NC; j += 4) {
            float4 X = *(const float4*)&sx[j];
            float4 Y = *(const float4*)&sy[j];
            float4 Z = *(const float4*)&sz[j];
            float4 W = *(const float4*)&sw[j];
            float sa = fmaf(fz, Z.x, fmaf(fy, Y.x, fmaf(fx, X.x, W.x)));
            float sb = fmaf(fz, Z.y, fmaf(fy, Y.y, fmaf(fx, X.y, W.y)));
            float sc = fmaf(fz, Z.z, fmaf(fy, Y.z, fmaf(fx, X.z, W.z)));
            float sd = fmaf(fz, Z.w, fmaf(fy, Y.w, fmaf(fx, X.w, W.w)));
            float smax = fmaxf(fmaxf(sa, sb), fmaxf(sc, sd));
            if (smax > a2) {
                ins3(sa, j+0, a0, a1, a2, ai0, ai1, ai2);
                ins3(sb, j+1, a0, a1, a2, ai0, ai1, ai2);
                ins3(sc, j+2, a0, a1, a2, ai0, ai1, ai2);
                ins3(sd, j+3, a0, a1, a2, ai0, ai1, ai2);
            }
        }

        // exact distances + weights for winners
        float dx, dy, dz;
        dx = fx - sx[ai0]; dy = fy - sy[ai0]; dz = fz - sz[ai0];
        float d0 = dx*dx + dy*dy + dz*dz;
        dx = fx - sx[ai1]; dy = fy - sy[ai1]; dz = fz - sz[ai1];
        float d1 = dx*dx + dy*dy + dz*dz;
        dx = fx - sx[ai2]; dy = fy - sy[ai2]; dz = fz - sz[ai2];
        float d2 = dx*dx + dy*dy + dz*dz;
        float w0 = 1.0f / fmaxf(d0, 1e-16f);
        float w1 = 1.0f / fmaxf(d1, 1e-16f);
        float w2 = 1.0f / fmaxf(d2, 1e-16f);
        float inv = 1.0f / (w0 + w1 + w2);
        g_idx[p*3+0] = b*NC + ai0;
        g_idx[p*3+1] = b*NC + ai1;
        g_idx[p*3+2] = b*NC + ai2;
        g_w[p*3+0] = w0 * inv;
        g_w[p*3+1] = w1 * inv;
        g_w[p*3+2] = w2 * inv;
    } else if (blk < 256 + 80) {
        // ---- weight prep: W^T -> B-fragment hi/lo ----
        int t = (blk - 256) * 256 + tid;
        if (t < NNB * NKB1 * 32) {
            int lane = t & 31;
            int kb = (t >> 5) % NKB1;
            int nb = t / (32 * NKB1);
            int n = nb*8 + (lane >> 2);
            int k0 = kb*16 + (lane & 3)*2;
            float v0 = W1[(k0+0)*OUTD + n], v1 = W1[(k0+1)*OUTD + n];
            float v8 = W1[(k0+8)*OUTD + n], v9 = W1[(k0+9)*OUTD + n];
            uint32_t h0, l0, h1, l1;
            split2(v0, v1, h0, l0);
            split2(v8, v9, h1, l1);
            int idx = (nb*NKB1 + kb)*64 + lane*2;
            g_w1f_hi[idx] = h0; g_w1f_hi[idx+1] = h1;
            g_w1f_lo[idx] = l0; g_w1f_lo[idx+1] = l1;
        }
        if (t < NNB * NKB2 * 32) {
            int lane = t & 31;
            int kb = (t >> 5) & 15;
            int nb = t >> 9;
            int n = nb*8 + (lane >> 2);
            int k0 = kb*16 + (lane & 3)*2;
            float v0 = W2[(k0+0)*OUTD + n], v1 = W2[(k0+1)*OUTD + n];
            float v8 = W2[(k0+8)*OUTD + n], v9 = W2[(k0+9)*OUTD + n];
            uint32_t h0, l0, h1, l1;
            split2(v0, v1, h0, l0);
            split2(v8, v9, h1, l1);
            int idx = (nb*NKB2 + kb)*64 + lane*2;
            g_w2f_hi[idx] = h0; g_w2f_hi[idx+1] = h1;
            g_w2f_lo[idx] = l0; g_w2f_lo[idx+1] = l1;
        }
    } else {
        // ---- aux tail: pos_skip + batch_skip ----
        int i = (blk - 336) * 256 + tid;
        if (i < MTOT*3) out[HSIZE + i] = pos_skip[i];
        if (i < MTOT)   out[HSIZE + MTOT*3 + i] = (float)batch_skip[i];
    }
}

// ---------------- GEMM1: pipelined gather+interp + Linear1 + ReLU -> h fragments ----------------
#define RS 40   // smem row stride (bf16)

__global__ __launch_bounds__(256, 2)
void gemm1_kernel(const float* __restrict__ x,
                  const float* __restrict__ x_skip,
                  const float* __restrict__ b1) {
    __shared__ __nv_bfloat16 As_hi[2][64*RS], As_lo[2][64*RS];

    int tid = threadIdx.x;
    int wid = tid >> 5;
    int lane = tid & 31;
    int warp_m = wid & 1;      // 2 m-strips of 32 rows
    int warp_n = wid >> 1;     // 4 n-quarters of 64 cols
    int bm = blockIdx.x * 64;

    int lrow = tid >> 2;       // 0..63
    int koff = (tid & 3) * 8;  // 0,8,16,24
    int r = bm + lrow;
    int i0 = g_idx[r*3+0] * CDIM, i1 = g_idx[r*3+1] * CDIM, i2 = g_idx[r*3+2] * CDIM;
    float w0 = g_w[r*3+0], w1 = g_w[r*3+1], w2 = g_w[r*3+2];
    int sbase = lrow * RS + koff;

    uint32_t aOff = (uint32_t)(((warp_m*32 + (lane & 15)) * RS + (lane >> 4) * 8) * 2);
    uint32_t sH[2] = { smem_u32(As_hi[0]) + aOff, smem_u32(As_hi[1]) + aOff };
    uint32_t sL[2] = { smem_u32(As_lo[0]) + aOff, smem_u32(As_lo[1]) + aOff };

    float acc[2][8][4];
    #pragma unroll
    for (int i = 0; i < 2; i++)
        #pragma unroll
        for (int j = 0; j < 8; j++)
            #pragma unroll
            for (int q = 0; q < 4; q++) acc[i][j][q] = 0.0f;

    // ---- prologue: build chunk 0 into buf 0 ----
    {
        float4 a0 = *(const float4*)(x + i0 + koff);
        float4 a1 = *(const float4*)(x + i0 + koff + 4);
        float4 b0 = *(const float4*)(x + i1 + koff);
        float4 b1v = *(const float4*)(x + i1 + koff + 4);
        float4 c0 = *(const float4*)(x + i2 + koff);
        float4 c1 = *(const float4*)(x + i2 + koff + 4);
        uint32_t hp[4], lp[4];
        split2(w0*a0.x + w1*b0.x + w2*c0.x,  w0*a0.y + w1*b0.y + w2*c0.y,  hp[0], lp[0]);
        split2(w0*a0.z + w1*b0.z + w2*c0.z,  w0*a0.w + w1*b0.w + w2*c0.w,  hp[1], lp[1]);
        split2(w0*a1.x + w1*b1v.x + w2*c1.x, w0*a1.y + w1*b1v.y + w2*c1.y, hp[2], lp[2]);
        split2(w0*a1.z + w1*b1v.z + w2*c1.z, w0*a1.w + w1*b1v.w + w2*c1.w, hp[3], lp[3]);
        *(uint4*)(As_hi[0] + sbase) = make_uint4(hp[0], hp[1], hp[2], hp[3]);
        *(uint4*)(As_lo[0] + sbase) = make_uint4(lp[0], lp[1], lp[2], lp[3]);
    }
    __syncthreads();

    for (int c = 0; c < 10; c++) {
        int buf = c & 1;
        float4 ga0, ga1, gb0, gb1, gc0, gc1;
        bool have_next = (c + 1 < 10);
        bool next_is_x = ((c + 1) * 32 < CDIM);
        if (have_next) {
            if (next_is_x) {
                int k = (c + 1) * 32 + koff;
                ga0 = *(const float4*)(x + i0 + k);
                ga1 = *(const float4*)(x + i0 + k + 4);
                gb0 = *(const float4*)(x + i1 + k);
                gb1 = *(const float4*)(x + i1 + k + 4);
                gc0 = *(const float4*)(x + i2 + k);
                gc1 = *(const float4*)(x + i2 + k + 4);
            } else {
                int ks = (c + 1) * 32 - CDIM + koff;
                ga0 = *(const float4*)(x_skip + (size_t)r * CS + ks);
                ga1 = *(const float4*)(x_skip + (size_t)r * CS + ks + 4);
            }
        }

        #pragma unroll
        for (int ks = 0; ks < 2; ks++) {
            int kb = c*2 + ks;
            uint32_t ko = ks * 32;
            uint32_t ah[2][4], al[2][4];
            #pragma unroll
            for (int mt = 0; mt < 2; mt++) {
                LDSM_X4(ah[mt][0], ah[mt][1], ah[mt][2], ah[mt][3], sH[buf] + mt*16*RS*2 + ko);
                LDSM_X4(al[mt][0], al[mt][1], al[mt][2], al[mt][3], sL[buf] + mt*16*RS*2 + ko);
            }
            #pragma unroll
            for (int nb = 0; nb < 8; nb++) {
                int nblock = warp_n*8 + nb;
                uint2 bh = *(const uint2*)&g_w1f_hi[(nblock*NKB1 + kb)*64 + lane*2];
                uint2 bl = *(const uint2*)&g_w1f_lo[(nblock*NKB1 + kb)*64 + lane*2];
                #pragma unroll
                for (int mt = 0; mt < 2; mt++) {
                    float* d = acc[mt][nb];
                    MMA_BF16(d, ah[mt], bh.x, bh.y);
                    MMA_BF16(d, ah[mt], bl.x, bl.y);
                    MMA_BF16(d, al[mt], bh.x, bh.y);
                }
            }
        }

        if (have_next) {
            float v[8];
            if (next_is_x) {
                v[0] = w0*ga0.x + w1*gb0.x + w2*gc0.x;
                v[1] = w0*ga0.y + w1*gb0.y + w2*gc0.y;
                v[2] = w0*ga0.z + w1*gb0.z + w2*gc0.z;
                v[3] = w0*ga0.w + w1*gb0.w + w2*gc0.w;
                v[4] = w0*ga1.x + w1*gb1.x + w2*gc1.x;
                v[5] = w0*ga1.y + w1*gb1.y + w2*gc1.y;
                v[6] = w0*ga1.z + w1*gb1.z + w2*gc1.z;
                v[7] = w0*ga1.w + w1*gb1.w + w2*gc1.w;
            } else {
                v[0] = ga0.x; v[1] = ga0.y; v[2] = ga0.z; v[3] = ga0.w;
                v[4] = ga1.x; v[5] = ga1.y; v[6] = ga1.z; v[7] = ga1.w;
            }
            uint32_t hp[4], lp[4];
            split2(v[0], v[1], hp[0], lp[0]);
            split2(v[2], v[3], hp[1], lp[1]);
            split2(v[4], v[5], hp[2], lp[2]);
            split2(v[6], v[7], hp[3], lp[3]);
            *(uint4*)(As_hi[buf^1] + sbase) = make_uint4(hp[0], hp[1], hp[2], hp[3]);
            *(uint4*)(As_lo[buf^1] + sbase) = make_uint4(lp[0], lp[1], lp[2], lp[3]);
        }
        __syncthreads();
    }

    // ---- epilogue: bias + ReLU -> h A-fragments ----
    #pragma unroll
    for (int mt = 0; mt < 2; mt++) {
        int mblock = blockIdx.x*4 + warp_m*2 + mt;
        #pragma unroll
        for (int fp = 0; fp < 4; fp++) {
            int f0 = 2*fp, f1 = 2*fp + 1;
            int kbh = warp_n*4 + fp;
            int col0 = (warp_n*8 + f0)*8 + (lane & 3)*2;
            float2 bb0 = *(const float2*)(b1 + col0);
            float2 bb1 = *(const float2*)(b1 + col0 + 8);
            float v0 = fmaxf(acc[mt][f0][0] + bb0.x, 0.0f);
            float v1 = fmaxf(acc[mt][f0][1] + bb0.y, 0.0f);
            float v2 = fmaxf(acc[mt][f0][2] + bb0.x, 0.0f);
            float v3 = fmaxf(acc[mt][f0][3] + bb0.y, 0.0f);
            float v4 = fmaxf(acc[mt][f1][0] + bb1.x, 0.0f);
            float v5 = fmaxf(acc[mt][f1][1] + bb1.y, 0.0f);
            float v6 = fmaxf(acc[mt][f1][2] + bb1.x, 0.0f);
            float v7 = fmaxf(acc[mt][f1][3] + bb1.y, 0.0f);
            uint32_t a0h, a0l, a1h, a1l, a2h, a2l, a3h, a3l;
            split2(v0, v1, a0h, a0l);
            split2(v2, v3, a1h, a1l);
            split2(v4, v5, a2h, a2l);
            split2(v6, v7, a3h, a3l);
            int fidx = (mblock*NKB2 + kbh)*32 + lane;
            ((uint4*)g_hfrag_hi)[fidx] = make_uint4(a0h, a1h, a2h, a3h);
            ((uint4*)g_hfrag_lo)[fidx] = make_uint4(a0l, a1l, a2l, a3l);
        }
    }
}

// ---------------- GEMM2: Linear2 + ReLU, fragment path with reg double-buffer ----------------
__global__ __launch_bounds__(256, 2)
void gemm2_kernel(const float* __restrict__ b2, float* __restrict__ out) {
    int tid = threadIdx.x;
    int wid = tid >> 5;
    int lane = tid & 31;
    int g = blockIdx.x * 8 + wid;
    int mstrip = g >> 2;
    int nq = g & 3;

    const uint4* HF = (const uint4*)g_hfrag_hi;
    const uint4* LF = (const uint4*)g_hfrag_lo;
    int mb0 = mstrip * 2;

    float acc[2][8][4];
    #pragma unroll
    for (int i = 0; i < 2; i++)
        #pragma unroll
        for (int j = 0; j < 8; j++)
            #pragma unroll
            for (int q = 0; q < 4; q++) acc[i][j][q] = 0.0f;

    uint4 th[2], tl[2];
    #pragma unroll
    for (int mt = 0; mt < 2; mt++) {
        th[mt] = HF[((mb0 + mt)*NKB2 + 0)*32 + lane];
        tl[mt] = LF[((mb0 + mt)*NKB2 + 0)*32 + lane];
    }

    for (int kb = 0; kb < NKB2; kb++) {
        uint32_t ah[2][4], al[2][4];
        #pragma unroll
        for (int mt = 0; mt < 2; mt++) {
            ah[mt][0] = th[mt].x; ah[mt][1] = th[mt].y; ah[mt][2] = th[mt].z; ah[mt][3] = th[mt].w;
            al[mt][0] = tl[mt].x; al[mt][1] = tl[mt].y; al[mt][2] = tl[mt].z; al[mt][3] = tl[mt].w;
        }
        if (kb + 1 < NKB2) {
            #pragma unroll
            for (int mt = 0; mt < 2; mt++) {
                th[mt] = HF[((mb0 + mt)*NKB2 + kb + 1)*32 + lane];
                tl[mt] = LF[((mb0 + mt)*NKB2 + kb + 1)*32 + lane];
            }
        }
        #pragma unroll
        for (int nb = 0; nb < 8; nb++) {
            int nblock = nq*8 + nb;
            uint2 bh = *(const uint2*)&g_w2f_hi[(nblock*NKB2 + kb)*64 + lane*2];
            uint2 bl = *(const uint2*)&g_w2f_lo[(nblock*NKB2 + kb)*64 + lane*2];
            #pragma unroll
            for (int mt = 0; mt < 2; mt++) {
                float* d = acc[mt][nb];
                MMA_BF16(d, ah[mt], bh.x, bh.y);
                MMA_BF16(d, ah[mt], bl.x, bl.y);
                MMA_BF16(d, al[mt], bh.x, bh.y);
            }
        }
    }

    #pragma unroll
    for (int mt = 0; mt < 2; mt++) {
        int r0 = mstrip*32 + mt*16 + (lane >> 2);
        #pragma unroll
        for (int nb = 0; nb < 8; nb++) {
            int col = (nq*8 + nb)*8 + (lane & 3)*2;
            float2 bb = *(const float2*)(b2 + col);
            float2 o0, o1;
            o0.x = fmaxf(acc[mt][nb][0] + bb.x, 0.0f);
            o0.y = fmaxf(acc[mt][nb][1] + bb.y, 0.0f);
            o1.x = fmaxf(acc[mt][nb][2] + bb.x, 0.0f);
            o1.y = fmaxf(acc[mt][nb][3] + bb.y, 0.0f);
            *(float2*)(out + (size_t)r0 * OUTD + col) = o0;
            *(float2*)(out + (size_t)(r0+8) * OUTD + col) = o1;
        }
    }
}

// ---------------- launch ----------------
extern "C" void kernel_launch(void* const* d_in, const int* in_sizes, int n_in,
                              void* d_out, int out_size) {
    const float* x          = (const float*)d_in[0];
    const float* pos        = (const float*)d_in[1];
    const float* x_skip     = (const float*)d_in[3];
    const float* pos_skip   = (const float*)d_in[4];
    const int*   batch_skip = (const int*)d_in[5];
    const float* W1         = (const float*)d_in[6];
    const float* b1         = (const float*)d_in[7];
    const float* W2         = (const float*)d_in[8];
    const float* b2         = (const float*)d_in[9];
    float* out = (float*)d_out;

    // knn: 256 blocks, prep: 80 blocks, aux: 768 blocks
    misc_kernel<<<256 + 80 + 768, 256>>>(pos, pos_skip, batch_skip, W1, W2, out);
    gemm1_kernel<<<MTOT/64, 256>>>(x, x_skip, b1);
    gemm2_kernel<<<1024, 256>>>(b2, out);
}

// round 13
// speedup vs baseline: 1.5218x; 1.0022x over previous
#include <cuda_runtime.h>
#include <cuda_bf16.h>
#include <cstdint>

// ---------------- problem constants ----------------
#define NB   8
#define NC   2048
#define NF   8192
#define CDIM 256
#define CS   64
#define OUTD 256
#define MTOT (NB*NF)        // 65536
#define K1   (CDIM+CS)      // 320
#define HSIZE (MTOT*OUTD)
#define NKB1 20             // K1/16 k-blocks for GEMM1
#define NKB2 16             // 256/16 k-blocks for GEMM2
#define NNB  32             // 256/8 n-blocks
#define HALF 1024           // candidates per KNN phase-A block

// ---------------- scratch (static device globals) ----------------
__device__ int   g_idx[MTOT*3];
__device__ float g_w[MTOT*3];
__device__ float g_ps[2*MTOT*3];   // partial top-3 scores   [half][point][3]
__device__ int   g_pi[2*MTOT*3];   // partial top-3 global idx
__device__ __align__(16) uint32_t g_hfrag_hi[(MTOT/16)*NKB2*128];
__device__ __align__(16) uint32_t g_hfrag_lo[(MTOT/16)*NKB2*128];
__device__ __align__(16) uint32_t g_w1f_hi[NNB*NKB1*64];
__device__ __align__(16) uint32_t g_w1f_lo[NNB*NKB1*64];
__device__ __align__(16) uint32_t g_w2f_hi[NNB*NKB2*64];
__device__ __align__(16) uint32_t g_w2f_lo[NNB*NKB2*64];

// ---------------- helpers ----------------
__device__ __forceinline__ uint32_t smem_u32(const void* p) {
    uint32_t a;
    asm("{ .reg .u64 t; cvta.to.shared.u64 t, %1; cvt.u32.u64 %0, t; }" : "=r"(a) : "l"(p));
    return a;
}

#define LDSM_X4(r0, r1, r2, r3, addr) \
    asm volatile("ldmatrix.sync.aligned.m8n8.x4.shared.b16 {%0,%1,%2,%3}, [%4];" \
        : "=r"(r0), "=r"(r1), "=r"(r2), "=r"(r3) : "r"(addr))

#define MMA_BF16(d, a, b0, b1) \
    asm volatile("mma.sync.aligned.m16n8k16.row.col.f32.bf16.bf16.f32 " \
        "{%0,%1,%2,%3}, {%4,%5,%6,%7}, {%8,%9}, {%0,%1,%2,%3};" \
        : "+f"((d)[0]), "+f"((d)[1]), "+f"((d)[2]), "+f"((d)[3]) \
        : "r"((a)[0]), "r"((a)[1]), "r"((a)[2]), "r"((a)[3]), "r"(b0), "r"(b1))

__device__ __forceinline__ void split2(float v0, float v1, uint32_t& hi, uint32_t& lo) {
    __nv_bfloat16 h0 = __float2bfloat16(v0);
    __nv_bfloat16 h1 = __float2bfloat16(v1);
    __nv_bfloat16 l0 = __float2bfloat16(v0 - __bfloat162float(h0));
    __nv_bfloat16 l1 = __float2bfloat16(v1 - __bfloat162float(h1));
    hi = ((uint32_t)__bfloat16_as_ushort(h1) << 16) | (uint32_t)__bfloat16_as_ushort(h0);
    lo = ((uint32_t)__bfloat16_as_ushort(l1) << 16) | (uint32_t)__bfloat16_as_ushort(l0);
}

__device__ __forceinline__ void ins3(float s, int j,
                                     float& s0, float& s1, float& s2,
                                     int& i0, int& i1, int& i2) {
    if (s > s2) {
        if (s > s1) {
            s2 = s1; i2 = i1;
            if (s > s0) { s1 = s0; i1 = i0; s0 = s; i0 = j; }
            else        { s1 = s;  i1 = j; }
        } else { s2 = s; i2 = j; }
    }
}

// ---------------- fused misc: knnA (0..511), prep (512..591), aux (592..1359) ----------------
__global__ void misc_kernel(const float* __restrict__ pos,
                            const float* __restrict__ pos_skip,
                            const int*  __restrict__ batch_skip,
                            const float* __restrict__ W1,
                            const float* __restrict__ W2,
                            float* __restrict__ out) {
    __shared__ float sx[HALF], sy[HALF], sz[HALF], sw[HALF];
    int blk = blockIdx.x;
    int tid = threadIdx.x;

    if (blk < 512) {
        // ---- KNN phase A: half-range scan, 256 points/block ----
        int half = blk & 1;
        int grp = blk >> 1;          // 0..255
        int b = grp >> 5;
        int blk_in = grp & 31;
        int jbase = half * HALF;
        const float* cp = pos + ((size_t)b * NC + jbase) * 3;
        for (int i = tid; i < HALF; i += 256) {
            float cx = cp[i*3+0], cy = cp[i*3+1], cz = cp[i*3+2];
            sx[i] = cx; sy[i] = cy; sz[i] = cz;
            sw[i] = -0.5f * (cx*cx + cy*cy + cz*cz);
        }
        __syncthreads();

        int p = b * NF + blk_in * 256 + tid;
        float fx = pos_skip[p*3+0], fy = pos_skip[p*3+1], fz = pos_skip[p*3+2];

        float a0 = -1e30f, a1 = -1e30f, a2 = -1e30f;
        int   ai0 = 0,     ai1 = 0,     ai2 = 0;

        #pragma unroll 2
        for (int j = 0; j < HALF; j += 4) {
            float4 X = *(const float4*)&sx[j];
            float4 Y = *(const float4*)&sy[j];
            float4 Z = *(const float4*)&sz[j];
            float4 W = *(const float4*)&sw[j];
            float sa = fmaf(fz, Z.x, fmaf(fy, Y.x, fmaf(fx, X.x, W.x)));
            float sb = fmaf(fz, Z.y, fmaf(fy, Y.y, fmaf(fx, X.y, W.y)));
            float sc = fmaf(fz, Z.z, fmaf(fy, Y.z, fmaf(fx, X.z, W.z)));
            float sd = fmaf(fz, Z.w, fmaf(fy, Y.w, fmaf(fx, X.w, W.w)));
            float smax = fmaxf(fmaxf(sa, sb), fmaxf(sc, sd));
            if (smax > a2) {
                ins3(sa, j+0, a0, a1, a2, ai0, ai1, ai2);
                ins3(sb, j+1, a0, a1, a2, ai0, ai1, ai2);
                ins3(sc, j+2, a0, a1, a2, ai0, ai1, ai2);
                ins3(sd, j+3, a0, a1, a2, ai0, ai1, ai2);
            }
        }

        // store partial results (global candidate index)
        int base = (half * MTOT + p) * 3;
        g_ps[base+0] = a0; g_ps[base+1] = a1; g_ps[base+2] = a2;
        g_pi[base+0] = b*NC + jbase + ai0;
        g_pi[base+1] = b*NC + jbase + ai1;
        g_pi[base+2] = b*NC + jbase + ai2;
    } else if (blk < 512 + 80) {
        // ---- weight prep: W^T -> B-fragment hi/lo ----
        int t = (blk - 512) * 256 + tid;
        if (t < NNB * NKB1 * 32) {
            int lane = t & 31;
            int kb = (t >> 5) % NKB1;
            int nb = t / (32 * NKB1);
            int n = nb*8 + (lane >> 2);
            int k0 = kb*16 + (lane & 3)*2;
            float v0 = W1[(k0+0)*OUTD + n], v1 = W1[(k0+1)*OUTD + n];
            float v8 = W1[(k0+8)*OUTD + n], v9 = W1[(k0+9)*OUTD + n];
            uint32_t h0, l0, h1, l1;
            split2(v0, v1, h0, l0);
            split2(v8, v9, h1, l1);
            int idx = (nb*NKB1 + kb)*64 + lane*2;
            g_w1f_hi[idx] = h0; g_w1f_hi[idx+1] = h1;
            g_w1f_lo[idx] = l0; g_w1f_lo[idx+1] = l1;
        }
        if (t < NNB * NKB2 * 32) {
            int lane = t & 31;
            int kb = (t >> 5) & 15;
            int nb = t >> 9;
            int n = nb*8 + (lane >> 2);
            int k0 = kb*16 + (lane & 3)*2;
            float v0 = W2[(k0+0)*OUTD + n], v1 = W2[(k0+1)*OUTD + n];
            float v8 = W2[(k0+8)*OUTD + n], v9 = W2[(k0+9)*OUTD + n];
            uint32_t h0, l0, h1, l1;
            split2(v0, v1, h0, l0);
            split2(v8, v9, h1, l1);
            int idx = (nb*NKB2 + kb)*64 + lane*2;
            g_w2f_hi[idx] = h0; g_w2f_hi[idx+1] = h1;
            g_w2f_lo[idx] = l0; g_w2f_lo[idx+1] = l1;
        }
    } else {
        // ---- aux tail: pos_skip + batch_skip ----
        int i = (blk - 592) * 256 + tid;
        if (i < MTOT*3) out[HSIZE + i] = pos_skip[i];
        if (i < MTOT)   out[HSIZE + MTOT*3 + i] = (float)batch_skip[i];
    }
}

// ---------------- KNN phase B: merge halves, exact distances, weights ----------------
__global__ void knn_merge_kernel(const float* __restrict__ pos,
                                 const float* __restrict__ pos_skip) {
    int p = blockIdx.x * 256 + threadIdx.x;
    int b0 = p * 3;
    int b1 = (MTOT + p) * 3;

    // half0 list (already sorted desc, lower indices)
    float s0 = g_ps[b0+0], s1 = g_ps[b0+1], s2 = g_ps[b0+2];
    int   i0 = g_pi[b0+0], i1 = g_pi[b0+1], i2 = g_pi[b0+2];
    // insert half1 entries in order; strict > keeps half0 (lower idx) on ties
    ins3(g_ps[b1+0], g_pi[b1+0], s0, s1, s2, i0, i1, i2);
    ins3(g_ps[b1+1], g_pi[b1+1], s0, s1, s2, i0, i1, i2);
    ins3(g_ps[b1+2], g_pi[b1+2], s0, s1, s2, i0, i1, i2);

    float fx = pos_skip[p*3+0], fy = pos_skip[p*3+1], fz = pos_skip[p*3+2];
    float dx, dy, dz;
    dx = fx - pos[i0*3+0]; dy = fy - pos[i0*3+1]; dz = fz - pos[i0*3+2];
    float d0 = dx*dx + dy*dy + dz*dz;
    dx = fx - pos[i1*3+0]; dy = fy - pos[i1*3+1]; dz = fz - pos[i1*3+2];
    float d1 = dx*dx + dy*dy + dz*dz;
    dx = fx - pos[i2*3+0]; dy = fy - pos[i2*3+1]; dz = fz - pos[i2*3+2];
    float d2 = dx*dx + dy*dy + dz*dz;
    float w0 = 1.0f / fmaxf(d0, 1e-16f);
    float w1 = 1.0f / fmaxf(d1, 1e-16f);
    float w2 = 1.0f / fmaxf(d2, 1e-16f);
    float inv = 1.0f / (w0 + w1 + w2);
    g_idx[p*3+0] = i0;
    g_idx[p*3+1] = i1;
    g_idx[p*3+2] = i2;
    g_w[p*3+0] = w0 * inv;
    g_w[p*3+1] = w1 * inv;
    g_w[p*3+2] = w2 * inv;
}

// ---------------- GEMM1: pipelined gather+interp + Linear1 + ReLU -> h fragments ----------------
#define RS 40   // smem row stride (bf16)

__global__ __launch_bounds__(256, 2)
void gemm1_kernel(const float* __restrict__ x,
                  const float* __restrict__ x_skip,
                  const float* __restrict__ b1) {
    __shared__ __nv_bfloat16 As_hi[2][64*RS], As_lo[2][64*RS];

    int tid = threadIdx.x;
    int wid = tid >> 5;
    int lane = tid & 31;
    int warp_m = wid & 1;      // 2 m-strips of 32 rows
    int warp_n = wid >> 1;     // 4 n-quarters of 64 cols
    int bm = blockIdx.x * 64;

    int lrow = tid >> 2;       // 0..63
    int koff = (tid & 3) * 8;  // 0,8,16,24
    int r = bm + lrow;
    int i0 = g_idx[r*3+0] * CDIM, i1 = g_idx[r*3+1] * CDIM, i2 = g_idx[r*3+2] * CDIM;
    float w0 = g_w[r*3+0], w1 = g_w[r*3+1], w2 = g_w[r*3+2];
    int sbase = lrow * RS + koff;

    uint32_t aOff = (uint32_t)(((warp_m*32 + (lane & 15)) * RS + (lane >> 4) * 8) * 2);
    uint32_t sH[2] = { smem_u32(As_hi[0]) + aOff, smem_u32(As_hi[1]) + aOff };
    uint32_t sL[2] = { smem_u32(As_lo[0]) + aOff, smem_u32(As_lo[1]) + aOff };

    float acc[2][8][4];
    #pragma unroll
    for (int i = 0; i < 2; i++)
        #pragma unroll
        for (int j = 0; j < 8; j++)
            #pragma unroll
            for (int q = 0; q < 4; q++) acc[i][j][q] = 0.0f;

    // ---- prologue: build chunk 0 into buf 0 ----
    {
        float4 a0 = *(const float4*)(x + i0 + koff);
        float4 a1 = *(const float4*)(x + i0 + koff + 4);
        float4 b0 = *(const float4*)(x + i1 + koff);
        float4 b1v = *(const float4*)(x + i1 + koff + 4);
        float4 c0 = *(const float4*)(x + i2 + koff);
        float4 c1 = *(const float4*)(x + i2 + koff + 4);
        uint32_t hp[4], lp[4];
        split2(w0*a0.x + w1*b0.x + w2*c0.x,  w0*a0.y + w1*b0.y + w2*c0.y,  hp[0], lp[0]);
        split2(w0*a0.z + w1*b0.z + w2*c0.z,  w0*a0.w + w1*b0.w + w2*c0.w,  hp[1], lp[1]);
        split2(w0*a1.x + w1*b1v.x + w2*c1.x, w0*a1.y + w1*b1v.y + w2*c1.y, hp[2], lp[2]);
        split2(w0*a1.z + w1*b1v.z + w2*c1.z, w0*a1.w + w1*b1v.w + w2*c1.w, hp[3], lp[3]);
        *(uint4*)(As_hi[0] + sbase) = make_uint4(hp[0], hp[1], hp[2], hp[3]);
        *(uint4*)(As_lo[0] + sbase) = make_uint4(lp[0], lp[1], lp[2], lp[3]);
    }
    __syncthreads();

    for (int c = 0; c < 10; c++) {
        int buf = c & 1;
        float4 ga0, ga1, gb0, gb1, gc0, gc1;
        bool have_next = (c + 1 < 10);
        bool next_is_x = ((c + 1) * 32 < CDIM);
        if (have_next) {
            if (next_is_x) {
                int k = (c + 1) * 32 + koff;
                ga0 = *(const float4*)(x + i0 + k);
                ga1 = *(const float4*)(x + i0 + k + 4);
                gb0 = *(const float4*)(x + i1 + k);
                gb1 = *(const float4*)(x + i1 + k + 4);
                gc0 = *(const float4*)(x + i2 + k);
                gc1 = *(const float4*)(x + i2 + k + 4);
            } else {
                int ks = (c + 1) * 32 - CDIM + koff;
                ga0 = *(const float4*)(x_skip + (size_t)r * CS + ks);
                ga1 = *(const float4*)(x_skip + (size_t)r * CS + ks + 4);
            }
        }

        #pragma unroll
        for (int ks = 0; ks < 2; ks++) {
            int kb = c*2 + ks;
            uint32_t ko = ks * 32;
            uint32_t ah[2][4], al[2][4];
            #pragma unroll
            for (int mt = 0; mt < 2; mt++) {
                LDSM_X4(ah[mt][0], ah[mt][1], ah[mt][2], ah[mt][3], sH[buf] + mt*16*RS*2 + ko);
                LDSM_X4(al[mt][0], al[mt][1], al[mt][2], al[mt][3], sL[buf] + mt*16*RS*2 + ko);
            }
            #pragma unroll
            for (int nb = 0; nb < 8; nb++) {
                int nblock = warp_n*8 + nb;
                uint2 bh = *(const uint2*)&g_w1f_hi[(nblock*NKB1 + kb)*64 + lane*2];
                uint2 bl = *(const uint2*)&g_w1f_lo[(nblock*NKB1 + kb)*64 + lane*2];
                #pragma unroll
                for (int mt = 0; mt < 2; mt++) {
                    float* d = acc[mt][nb];
                    MMA_BF16(d, ah[mt], bh.x, bh.y);
                    MMA_BF16(d, ah[mt], bl.x, bl.y);
                    MMA_BF16(d, al[mt], bh.x, bh.y);
                }
            }
        }

        if (have_next) {
            float v[8];
            if (next_is_x) {
                v[0] = w0*ga0.x + w1*gb0.x + w2*gc0.x;
                v[1] = w0*ga0.y + w1*gb0.y + w2*gc0.y;
                v[2] = w0*ga0.z + w1*gb0.z + w2*gc0.z;
                v[3] = w0*ga0.w + w1*gb0.w + w2*gc0.w;
                v[4] = w0*ga1.x + w1*gb1.x + w2*gc1.x;
                v[5] = w0*ga1.y + w1*gb1.y + w2*gc1.y;
                v[6] = w0*ga1.z + w1*gb1.z + w2*gc1.z;
                v[7] = w0*ga1.w + w1*gb1.w + w2*gc1.w;
            } else {
                v[0] = ga0.x; v[1] = ga0.y; v[2] = ga0.z; v[3] = ga0.w;
                v[4] = ga1.x; v[5] = ga1.y; v[6] = ga1.z; v[7] = ga1.w;
            }
            uint32_t hp[4], lp[4];
            split2(v[0], v[1], hp[0], lp[0]);
            split2(v[2], v[3], hp[1], lp[1]);
            split2(v[4], v[5], hp[2], lp[2]);
            split2(v[6], v[7], hp[3], lp[3]);
            *(uint4*)(As_hi[buf^1] + sbase) = make_uint4(hp[0], hp[1], hp[2], hp[3]);
            *(uint4*)(As_lo[buf^1] + sbase) = make_uint4(lp[0], lp[1], lp[2], lp[3]);
        }
        __syncthreads();
    }

    // ---- epilogue: bias + ReLU -> h A-fragments ----
    #pragma unroll
    for (int mt = 0; mt < 2; mt++) {
        int mblock = blockIdx.x*4 + warp_m*2 + mt;
        #pragma unroll
        for (int fp = 0; fp < 4; fp++) {
            int f0 = 2*fp, f1 = 2*fp + 1;
            int kbh = warp_n*4 + fp;
            int col0 = (warp_n*8 + f0)*8 + (lane & 3)*2;
            float2 bb0 = *(const float2*)(b1 + col0);
            float2 bb1 = *(const float2*)(b1 + col0 + 8);
            float v0 = fmaxf(acc[mt][f0][0] + bb0.x, 0.0f);
            float v1 = fmaxf(acc[mt][f0][1] + bb0.y, 0.0f);
            float v2 = fmaxf(acc[mt][f0][2] + bb0.x, 0.0f);
            float v3 = fmaxf(acc[mt][f0][3] + bb0.y, 0.0f);
            float v4 = fmaxf(acc[mt][f1][0] + bb1.x, 0.0f);
            float v5 = fmaxf(acc[mt][f1][1] + bb1.y, 0.0f);
            float v6 = fmaxf(acc[mt][f1][2] + bb1.x, 0.0f);
            float v7 = fmaxf(acc[mt][f1][3] + bb1.y, 0.0f);
            uint32_t a0h, a0l, a1h, a1l, a2h, a2l, a3h, a3l;
            split2(v0, v1, a0h, a0l);
            split2(v2, v3, a1h, a1l);
            split2(v4, v5, a2h, a2l);
            split2(v6, v7, a3h, a3l);
            int fidx = (mblock*NKB2 + kbh)*32 + lane;
            ((uint4*)g_hfrag_hi)[fidx] = make_uint4(a0h, a1h, a2h, a3h);
            ((uint4*)g_hfrag_lo)[fidx] = make_uint4(a0l, a1l, a2l, a3l);
        }
    }
}

// ---------------- GEMM2: Linear2 + ReLU, fragment path with reg double-buffer ----------------
__global__ __launch_bounds__(256, 2)
void gemm2_kernel(const float* __restrict__ b2, float* __restrict__ out) {
    int tid = threadIdx.x;
    int wid = tid >> 5;
    int lane = tid & 31;
    int g = blockIdx.x * 8 + wid;
    int mstrip = g >> 2;
    int nq = g & 3;

    const uint4* HF = (const uint4*)g_hfrag_hi;
    const uint4* LF = (const uint4*)g_hfrag_lo;
    int mb0 = mstrip * 2;

    float acc[2][8][4];
    #pragma unroll
    for (int i = 0; i < 2; i++)
        #pragma unroll
        for (int j = 0; j < 8; j++)
            #pragma unroll
            for (int q = 0; q < 4; q++) acc[i][j][q] = 0.0f;

    uint4 th[2], tl[2];
    #pragma unroll
    for (int mt = 0; mt < 2; mt++) {
        th[mt] = HF[((mb0 + mt)*NKB2 + 0)*32 + lane];
        tl[mt] = LF[((mb0 + mt)*NKB2 + 0)*32 + lane];
    }

    for (int kb = 0; kb < NKB2; kb++) {
        uint32_t ah[2][4], al[2][4];
        #pragma unroll
        for (int mt = 0; mt < 2; mt++) {
            ah[mt][0] = th[mt].x; ah[mt][1] = th[mt].y; ah[mt][2] = th[mt].z; ah[mt][3] = th[mt].w;
            al[mt][0] = tl[mt].x; al[mt][1] = tl[mt].y; al[mt][2] = tl[mt].z; al[mt][3] = tl[mt].w;
        }
        if (kb + 1 < NKB2) {
            #pragma unroll
            for (int mt = 0; mt < 2; mt++) {
                th[mt] = HF[((mb0 + mt)*NKB2 + kb + 1)*32 + lane];
                tl[mt] = LF[((mb0 + mt)*NKB2 + kb + 1)*32 + lane];
            }
        }
        #pragma unroll
        for (int nb = 0; nb < 8; nb++) {
            int nblock = nq*8 + nb;
            uint2 bh = *(const uint2*)&g_w2f_hi[(nblock*NKB2 + kb)*64 + lane*2];
            uint2 bl = *(const uint2*)&g_w2f_lo[(nblock*NKB2 + kb)*64 + lane*2];
            #pragma unroll
            for (int mt = 0; mt < 2; mt++) {
                float* d = acc[mt][nb];
                MMA_BF16(d, ah[mt], bh.x, bh.y);
                MMA_BF16(d, ah[mt], bl.x, bl.y);
                MMA_BF16(d, al[mt], bh.x, bh.y);
            }
        }
    }

    #pragma unroll
    for (int mt = 0; mt < 2; mt++) {
        int r0 = mstrip*32 + mt*16 + (lane >> 2);
        #pragma unroll
        for (int nb = 0; nb < 8; nb++) {
            int col = (nq*8 + nb)*8 + (lane & 3)*2;
            float2 bb = *(const float2*)(b2 + col);
            float2 o0, o1;
            o0.x = fmaxf(acc[mt][nb][0] + bb.x, 0.0f);
            o0.y = fmaxf(acc[mt][nb][1] + bb.y, 0.0f);
            o1.x = fmaxf(acc[mt][nb][2] + bb.x, 0.0f);
            o1.y = fmaxf(acc[mt][nb][3] + bb.y, 0.0f);
            *(float2*)(out + (size_t)r0 * OUTD + col) = o0;
            *(float2*)(out + (size_t)(r0+8) * OUTD + col) = o1;
        }
    }
}

// ---------------- launch ----------------
extern "C" void kernel_launch(void* const* d_in, const int* in_sizes, int n_in,
                              void* d_out, int out_size) {
    const float* x          = (const float*)d_in[0];
    const float* pos        = (const float*)d_in[1];
    const float* x_skip     = (const float*)d_in[3];
    const float* pos_skip   = (const float*)d_in[4];
    const int*   batch_skip = (const int*)d_in[5];
    const float* W1         = (const float*)d_in[6];
    const float* b1         = (const float*)d_in[7];
    const float* W2         = (const float*)d_in[8];
    const float* b2         = (const float*)d_in[9];
    float* out = (float*)d_out;

    // knnA: 512 blocks, prep: 80 blocks, aux: 768 blocks
    misc_kernel<<<512 + 80 + 768, 256>>>(pos, pos_skip, batch_skip, W1, W2, out);
    knn_merge_kernel<<<MTOT/256, 256>>>(pos, pos_skip);
    gemm1_kernel<<<MTOT/64, 256>>>(x, x_skip, b1);
    gemm2_kernel<<<1024, 256>>>(b2, out);
}